// round 4
// baseline (speedup 1.0000x reference)
#include <cuda_runtime.h>
#include <math.h>

#define BATCH  8192
#define NNZ    32
#define FT_OUT 512
#define NTHREADS 64   // each thread owns FT_OUT/NTHREADS = 8 floats (one 256-bit load)

// 256-bit gather, non-coherent, pinned in L2 (only legal direct-evict_last form on this ptxas)
__device__ __forceinline__ void ldg256_resident(const float* p, float* r) {
    asm volatile("ld.global.nc.L2::evict_last.v8.b32 {%0,%1,%2,%3,%4,%5,%6,%7}, [%8];"
                 : "=f"(r[0]), "=f"(r[1]), "=f"(r[2]), "=f"(r[3]),
                   "=f"(r[4]), "=f"(r[5]), "=f"(r[6]), "=f"(r[7])
                 : "l"(p));
}

__global__ __launch_bounds__(NTHREADS)
void nnue_fwd_kernel(const int*    __restrict__ stm_idx,    // [BATCH, NNZ]
                     const int*    __restrict__ nstm_idx,   // [BATCH, NNZ]
                     const float*  __restrict__ values,     // [BATCH, NNZ]
                     const float*  __restrict__ W_ft,       // [FT_IN, FT_OUT]
                     const float*  __restrict__ b_ft,       // [FT_OUT]
                     const float*  __restrict__ W_out,      // [2*FT_OUT]
                     const float*  __restrict__ b_out,      // [1]
                     float*        __restrict__ out)        // [BATCH]
{
    const int b = blockIdx.x;
    const int t = threadIdx.x;            // 0..63 -> 8-float column slot

    __shared__ int   s_off[2 * NNZ];      // pre-scaled row offsets (idx * FT_OUT)
    __shared__ float s_val[NNZ];
    __shared__ float s_red[NTHREADS / 32];

    if (t < NNZ) {
        s_off[t]       = __ldcs(&stm_idx [b * NNZ + t]) * FT_OUT;
        s_off[NNZ + t] = __ldcs(&nstm_idx[b * NNZ + t]) * FT_OUT;
        s_val[t]       = __ldcs(&values  [b * NNZ + t]);
    }
    __syncthreads();

    const float* Wcol = W_ft + 8 * t;     // this thread's 32-byte column slice

    float acc_s[8] = {0.f, 0.f, 0.f, 0.f, 0.f, 0.f, 0.f, 0.f};
    float acc_n[8] = {0.f, 0.f, 0.f, 0.f, 0.f, 0.f, 0.f, 0.f};

    #pragma unroll 8
    for (int k = 0; k < NNZ; k++) {
        float ws[8], wn[8];
        ldg256_resident(Wcol + s_off[k],       ws);
        ldg256_resident(Wcol + s_off[NNZ + k], wn);
        const float v = s_val[k];
        #pragma unroll
        for (int i = 0; i < 8; i++) {
            acc_s[i] = fmaf(v, ws[i], acc_s[i]);
            acc_n[i] = fmaf(v, wn[i], acc_n[i]);
        }
    }

    // bias + clamp [0,1] + dot with W_out slices (hidden = [stm | nstm])
    float p = 0.f;
    #pragma unroll
    for (int i = 0; i < 8; i++) {
        const float bb = __ldg(&b_ft[8 * t + i]);
        const float hs = fminf(fmaxf(acc_s[i] + bb, 0.f), 1.f);
        const float hn = fminf(fmaxf(acc_n[i] + bb, 0.f), 1.f);
        p = fmaf(hs, __ldg(&W_out[8 * t + i]),          p);
        p = fmaf(hn, __ldg(&W_out[FT_OUT + 8 * t + i]), p);
    }

    // warp reduce
    #pragma unroll
    for (int off = 16; off > 0; off >>= 1)
        p += __shfl_xor_sync(0xFFFFFFFFu, p, off);

    if ((t & 31) == 0) s_red[t >> 5] = p;
    __syncthreads();

    if (t == 0) {
        float s = s_red[0] + s_red[1] + __ldg(b_out);
        out[b] = 1.0f / (1.0f + expf(-s));
    }
}

extern "C" void kernel_launch(void* const* d_in, const int* in_sizes, int n_in,
                              void* d_out, int out_size)
{
    const int*   stm_idx  = (const int*)  d_in[0];
    const int*   nstm_idx = (const int*)  d_in[1];
    const float* values   = (const float*)d_in[2];
    const float* W_ft     = (const float*)d_in[3];
    const float* b_ft     = (const float*)d_in[4];
    const float* W_out    = (const float*)d_in[5];
    const float* b_out    = (const float*)d_in[6];
    float*       out      = (float*)      d_out;

    nnue_fwd_kernel<<<BATCH, NTHREADS>>>(stm_idx, nstm_idx, values,
                                         W_ft, b_ft, W_out, b_out, out);
}

// round 5
// speedup vs baseline: 1.1551x; 1.1551x over previous
#include <cuda_runtime.h>
#include <math.h>

#define BATCH  8192
#define NNZ    32
#define FT_OUT 512
#define NTHREADS 256   // t<128: stm half, t>=128: nstm half; each thread owns one float4 slot

__global__ __launch_bounds__(NTHREADS)
void nnue_fwd_kernel(const int*    __restrict__ stm_idx,    // [BATCH, NNZ]
                     const int*    __restrict__ nstm_idx,   // [BATCH, NNZ]
                     const float*  __restrict__ values,     // [BATCH, NNZ]
                     const float4* __restrict__ W_ft,       // [FT_IN, FT_OUT/4]
                     const float4* __restrict__ b_ft,       // [FT_OUT/4]
                     const float*  __restrict__ W_out,      // [2*FT_OUT]
                     const float*  __restrict__ b_out,      // [1]
                     float*        __restrict__ out)        // [BATCH]
{
    const int b    = blockIdx.x;
    const int t    = threadIdx.x;
    const int half = t >> 7;              // 0 = stm, 1 = nstm
    const int c    = t & 127;             // float4 column slot 0..127
    const int C    = FT_OUT / 4;          // 128 float4 per feature row

    __shared__ int   s_off[2 * NNZ];      // [stm offsets | nstm offsets], pre-scaled
    __shared__ float s_val[NNZ];
    __shared__ float s_red[NTHREADS / 32];

    if (t < NNZ) {
        s_off[t]       = __ldcs(&stm_idx [b * NNZ + t]) * C;
        s_off[NNZ + t] = __ldcs(&nstm_idx[b * NNZ + t]) * C;
        s_val[t]       = __ldcs(&values  [b * NNZ + t]);
    }
    __syncthreads();

    const int* my_off = &s_off[half * NNZ];

    float4 acc = make_float4(0.f, 0.f, 0.f, 0.f);

    #pragma unroll
    for (int k = 0; k < NNZ; k++) {
        const float  v = s_val[k];
        const float4 w = __ldg(&W_ft[my_off[k] + c]);
        acc.x = fmaf(v, w.x, acc.x);
        acc.y = fmaf(v, w.y, acc.y);
        acc.z = fmaf(v, w.z, acc.z);
        acc.w = fmaf(v, w.w, acc.w);
    }

    // bias + clamp [0,1]
    const float4 bb = __ldg(&b_ft[c]);
    const float h0 = fminf(fmaxf(acc.x + bb.x, 0.f), 1.f);
    const float h1 = fminf(fmaxf(acc.y + bb.y, 0.f), 1.f);
    const float h2 = fminf(fmaxf(acc.z + bb.z, 0.f), 1.f);
    const float h3 = fminf(fmaxf(acc.w + bb.w, 0.f), 1.f);

    // dot with the matching W_out half (hidden = [stm | nstm])
    const float4 wo = __ldg((const float4*)&W_out[half * FT_OUT + 4 * c]);
    float p = h0 * wo.x + h1 * wo.y + h2 * wo.z + h3 * wo.w;

    // warp reduce
    #pragma unroll
    for (int off = 16; off > 0; off >>= 1)
        p += __shfl_xor_sync(0xFFFFFFFFu, p, off);

    if ((t & 31) == 0) s_red[t >> 5] = p;
    __syncthreads();

    if (t == 0) {
        float s = s_red[0] + s_red[1] + s_red[2] + s_red[3]
                + s_red[4] + s_red[5] + s_red[6] + s_red[7] + __ldg(b_out);
        out[b] = 1.0f / (1.0f + expf(-s));
    }
}

extern "C" void kernel_launch(void* const* d_in, const int* in_sizes, int n_in,
                              void* d_out, int out_size)
{
    const int*    stm_idx  = (const int*)   d_in[0];
    const int*    nstm_idx = (const int*)   d_in[1];
    const float*  values   = (const float*) d_in[2];
    const float4* W_ft     = (const float4*)d_in[3];
    const float4* b_ft     = (const float4*)d_in[4];
    const float*  W_out    = (const float*) d_in[5];
    const float*  b_out    = (const float*) d_in[6];
    float*        out      = (float*)       d_out;

    nnue_fwd_kernel<<<BATCH, NTHREADS>>>(stm_idx, nstm_idx, values,
                                         W_ft, b_ft, W_out, b_out, out);
}

// round 6
// speedup vs baseline: 1.2327x; 1.0672x over previous
#include <cuda_runtime.h>
#include <cuda_bf16.h>
#include <math.h>

#define BATCH  8192
#define NNZ    32
#define FT_IN  40960
#define FT_OUT 512
#define ROWS_PER_CTA 2
#define NTHREADS 256   // 128 threads per batch row: 64 stm + 64 nstm, 8 cols each

// 40 MB bf16 copy of the feature table (static device scratch — no runtime alloc)
__device__ __nv_bfloat16 g_wft[FT_IN * FT_OUT];

// ---------------- Kernel 1: f32 -> bf16 table conversion (streaming) -------------
__global__ __launch_bounds__(256)
void convert_kernel(const float4* __restrict__ W_ft)
{
    const int i = blockIdx.x * 256 + threadIdx.x;   // group of 8 floats
    const float4 a = __ldcs(&W_ft[2 * i]);
    const float4 b = __ldcs(&W_ft[2 * i + 1]);
    __nv_bfloat162 p0 = __floats2bfloat162_rn(a.x, a.y);
    __nv_bfloat162 p1 = __floats2bfloat162_rn(a.z, a.w);
    __nv_bfloat162 p2 = __floats2bfloat162_rn(b.x, b.y);
    __nv_bfloat162 p3 = __floats2bfloat162_rn(b.z, b.w);
    uint4 o;
    o.x = *(unsigned*)&p0;  o.y = *(unsigned*)&p1;
    o.z = *(unsigned*)&p2;  o.w = *(unsigned*)&p3;
    ((uint4*)g_wft)[i] = o;
}

// ---------------- Kernel 2: sparse gather + MLP head from bf16 table -------------
__global__ __launch_bounds__(NTHREADS)
void nnue_fwd_kernel(const int*   __restrict__ stm_idx,    // [BATCH, NNZ]
                     const int*   __restrict__ nstm_idx,   // [BATCH, NNZ]
                     const float* __restrict__ values,     // [BATCH, NNZ]
                     const float* __restrict__ b_ft,       // [FT_OUT]
                     const float* __restrict__ W_out,      // [2*FT_OUT]
                     const float* __restrict__ b_out,      // [1]
                     float*       __restrict__ out)        // [BATCH]
{
    const int t  = threadIdx.x;
    const int r  = t >> 7;                 // row within CTA (0/1)
    const int lt = t & 127;                // lane within row group
    const int half = lt >> 6;              // 0 = stm, 1 = nstm
    const int c  = lt & 63;                // uint4 (8-col) slot 0..63
    const int b  = blockIdx.x * ROWS_PER_CTA + r;

    __shared__ int   s_off[ROWS_PER_CTA][2 * NNZ];  // idx * (FT_OUT/8), uint4 units
    __shared__ float s_val[ROWS_PER_CTA][NNZ];
    __shared__ float s_red[NTHREADS / 32];

    if (lt < NNZ) {
        s_off[r][lt]       = __ldcs(&stm_idx [b * NNZ + lt]) * (FT_OUT / 8);
        s_off[r][NNZ + lt] = __ldcs(&nstm_idx[b * NNZ + lt]) * (FT_OUT / 8);
        s_val[r][lt]       = __ldcs(&values  [b * NNZ + lt]);
    }
    __syncthreads();

    const int*   my_off = &s_off[r][half * NNZ];
    const uint4* tab    = (const uint4*)g_wft;      // row stride = FT_OUT/8 uint4

    float acc[8] = {0.f, 0.f, 0.f, 0.f, 0.f, 0.f, 0.f, 0.f};

    #pragma unroll
    for (int k = 0; k < NNZ; k++) {
        const uint4 w = __ldg(&tab[my_off[k] + c]);
        const float v = s_val[r][k];
        const __nv_bfloat162 w0 = *(const __nv_bfloat162*)&w.x;
        const __nv_bfloat162 w1 = *(const __nv_bfloat162*)&w.y;
        const __nv_bfloat162 w2 = *(const __nv_bfloat162*)&w.z;
        const __nv_bfloat162 w3 = *(const __nv_bfloat162*)&w.w;
        acc[0] = fmaf(v, __low2float (w0), acc[0]);
        acc[1] = fmaf(v, __high2float(w0), acc[1]);
        acc[2] = fmaf(v, __low2float (w1), acc[2]);
        acc[3] = fmaf(v, __high2float(w1), acc[3]);
        acc[4] = fmaf(v, __low2float (w2), acc[4]);
        acc[5] = fmaf(v, __high2float(w2), acc[5]);
        acc[6] = fmaf(v, __low2float (w3), acc[6]);
        acc[7] = fmaf(v, __high2float(w3), acc[7]);
    }

    // bias + clamp [0,1] + dot with matching W_out half (hidden = [stm | nstm])
    float p = 0.f;
    #pragma unroll
    for (int i = 0; i < 8; i++) {
        const float bb = __ldg(&b_ft[8 * c + i]);
        const float h  = fminf(fmaxf(acc[i] + bb, 0.f), 1.f);
        p = fmaf(h, __ldg(&W_out[half * FT_OUT + 8 * c + i]), p);
    }

    // warp reduce (each warp = 32 threads of one half-row slice)
    #pragma unroll
    for (int off = 16; off > 0; off >>= 1)
        p += __shfl_xor_sync(0xFFFFFFFFu, p, off);

    if ((t & 31) == 0) s_red[t >> 5] = p;
    __syncthreads();

    // warps 0-3 belong to row 0, warps 4-7 to row 1
    if ((t & 127) == 0) {
        const int w0 = r * 4;
        float s = s_red[w0] + s_red[w0 + 1] + s_red[w0 + 2] + s_red[w0 + 3]
                + __ldg(b_out);
        out[b] = 1.0f / (1.0f + expf(-s));
    }
}

extern "C" void kernel_launch(void* const* d_in, const int* in_sizes, int n_in,
                              void* d_out, int out_size)
{
    const int*    stm_idx  = (const int*)   d_in[0];
    const int*    nstm_idx = (const int*)   d_in[1];
    const float*  values   = (const float*) d_in[2];
    const float4* W_ft     = (const float4*)d_in[3];
    const float*  b_ft     = (const float*) d_in[4];
    const float*  W_out    = (const float*) d_in[5];
    const float*  b_out    = (const float*) d_in[6];
    float*        out      = (float*)       d_out;

    // 20,971,520 floats / 8 per thread / 256 threads = 10240 blocks
    convert_kernel<<<(FT_IN * FT_OUT) / (8 * 256), 256>>>(W_ft);
    nnue_fwd_kernel<<<BATCH / ROWS_PER_CTA, NTHREADS>>>(stm_idx, nstm_idx, values,
                                                        b_ft, W_out, b_out, out);
}

// round 7
// speedup vs baseline: 1.3688x; 1.1104x over previous
#include <cuda_runtime.h>
#include <cuda_bf16.h>
#include <math.h>

#define BATCH  8192
#define NNZ    32
#define FT_IN  40960
#define FT_OUT 512
#define ROWS_PER_CTA 2
#define NTHREADS 256   // 128 threads per batch row: 64 stm + 64 nstm, 8 cols each

// 40 MB bf16 copy of the feature table (static device scratch — no runtime alloc)
__device__ __nv_bfloat16 g_wft[FT_IN * FT_OUT];

// ---------------- Kernel 1: f32 -> bf16 table conversion (streaming) -------------
__global__ __launch_bounds__(256)
void convert_kernel(const float4* __restrict__ W_ft)
{
    const int i = blockIdx.x * 256 + threadIdx.x;   // group of 8 floats
    const float4 a = __ldcs(&W_ft[2 * i]);
    const float4 b = __ldcs(&W_ft[2 * i + 1]);
    __nv_bfloat162 p0 = __floats2bfloat162_rn(a.x, a.y);
    __nv_bfloat162 p1 = __floats2bfloat162_rn(a.z, a.w);
    __nv_bfloat162 p2 = __floats2bfloat162_rn(b.x, b.y);
    __nv_bfloat162 p3 = __floats2bfloat162_rn(b.z, b.w);
    uint4 o;
    o.x = *(unsigned*)&p0;  o.y = *(unsigned*)&p1;
    o.z = *(unsigned*)&p2;  o.w = *(unsigned*)&p3;
    ((uint4*)g_wft)[i] = o;
}

// f32 view of packed bf16 pair: low elem = shift, high elem = raw word (junk low
// bits perturb by <2^-9 relative — same order as the bf16 rounding already done)
__device__ __forceinline__ float bf_lo(unsigned w) { return __int_as_float((int)(w << 16)); }
__device__ __forceinline__ float bf_hi(unsigned w) { return __uint_as_float(w); }

// ---------------- Kernel 2: sparse gather + MLP head from bf16 table -------------
__global__ __launch_bounds__(NTHREADS)
void nnue_fwd_kernel(const int*   __restrict__ stm_idx,    // [BATCH, NNZ]
                     const int*   __restrict__ nstm_idx,   // [BATCH, NNZ]
                     const float* __restrict__ values,     // [BATCH, NNZ]
                     const float4* __restrict__ b_ft,      // [FT_OUT]
                     const float4* __restrict__ W_out,     // [2*FT_OUT]
                     const float* __restrict__ b_out,      // [1]
                     float*       __restrict__ out)        // [BATCH]
{
    const int t  = threadIdx.x;
    const int r  = t >> 7;                 // row within CTA (0/1)
    const int lt = t & 127;                // lane within row group
    const int half = lt >> 6;              // 0 = stm, 1 = nstm
    const int c  = lt & 63;                // uint4 (8-col) slot 0..63
    const int b  = blockIdx.x * ROWS_PER_CTA + r;

    __shared__ int   s_off[ROWS_PER_CTA][2 * NNZ];  // idx * (FT_OUT/8), uint4 units
    __shared__ float s_val[ROWS_PER_CTA][NNZ];
    __shared__ float s_red[NTHREADS / 32];

    if (lt < NNZ) {
        s_off[r][lt]       = __ldcs(&stm_idx [b * NNZ + lt]) * (FT_OUT / 8);
        s_off[r][NNZ + lt] = __ldcs(&nstm_idx[b * NNZ + lt]) * (FT_OUT / 8);
        s_val[r][lt]       = __ldcs(&values  [b * NNZ + lt]);
    }
    __syncthreads();

    const int*   my_off = &s_off[r][half * NNZ];
    const uint4* tab    = (const uint4*)g_wft + c;  // row stride = FT_OUT/8 uint4

    float acc[8] = {0.f, 0.f, 0.f, 0.f, 0.f, 0.f, 0.f, 0.f};

    #pragma unroll
    for (int k = 0; k < NNZ; k++) {
        const uint4 w = __ldg(tab + my_off[k]);
        const float v = s_val[r][k];
        acc[0] = fmaf(v, bf_lo(w.x), acc[0]);
        acc[1] = fmaf(v, bf_hi(w.x), acc[1]);
        acc[2] = fmaf(v, bf_lo(w.y), acc[2]);
        acc[3] = fmaf(v, bf_hi(w.y), acc[3]);
        acc[4] = fmaf(v, bf_lo(w.z), acc[4]);
        acc[5] = fmaf(v, bf_hi(w.z), acc[5]);
        acc[6] = fmaf(v, bf_lo(w.w), acc[6]);
        acc[7] = fmaf(v, bf_hi(w.w), acc[7]);
    }

    // bias + clamp [0,1] + dot with matching W_out half (hidden = [stm | nstm])
    const float4 bb0 = __ldg(&b_ft[2 * c]);
    const float4 bb1 = __ldg(&b_ft[2 * c + 1]);
    const float4 wo0 = __ldg(&W_out[half * (FT_OUT / 4) + 2 * c]);
    const float4 wo1 = __ldg(&W_out[half * (FT_OUT / 4) + 2 * c + 1]);
    const float* bbp = &bb0.x;   // contiguous float4 pair views
    const float* wop = &wo0.x;
    float bbv[8] = {bb0.x, bb0.y, bb0.z, bb0.w, bb1.x, bb1.y, bb1.z, bb1.w};
    float wov[8] = {wo0.x, wo0.y, wo0.z, wo0.w, wo1.x, wo1.y, wo1.z, wo1.w};
    (void)bbp; (void)wop;
    float p = 0.f;
    #pragma unroll
    for (int i = 0; i < 8; i++) {
        const float h = fminf(fmaxf(acc[i] + bbv[i], 0.f), 1.f);
        p = fmaf(h, wov[i], p);
    }

    // warp reduce (each warp = 32 threads of one half-row slice)
    #pragma unroll
    for (int off = 16; off > 0; off >>= 1)
        p += __shfl_xor_sync(0xFFFFFFFFu, p, off);

    if ((t & 31) == 0) s_red[t >> 5] = p;
    __syncthreads();

    // warps 0-3 belong to row 0, warps 4-7 to row 1
    if ((t & 127) == 0) {
        const int w0 = r * 4;
        float s = s_red[w0] + s_red[w0 + 1] + s_red[w0 + 2] + s_red[w0 + 3]
                + __ldg(b_out);
        out[b] = 1.0f / (1.0f + expf(-s));
    }
}

extern "C" void kernel_launch(void* const* d_in, const int* in_sizes, int n_in,
                              void* d_out, int out_size)
{
    const int*    stm_idx  = (const int*)   d_in[0];
    const int*    nstm_idx = (const int*)   d_in[1];
    const float*  values   = (const float*) d_in[2];
    const float4* W_ft     = (const float4*)d_in[3];
    const float4* b_ft     = (const float4*)d_in[4];
    const float4* W_out    = (const float4*)d_in[5];
    const float*  b_out    = (const float*) d_in[6];
    float*        out      = (float*)       d_out;

    // 20,971,520 floats / 8 per thread / 256 threads = 10240 blocks
    convert_kernel<<<(FT_IN * FT_OUT) / (8 * 256), 256>>>(W_ft);
    nnue_fwd_kernel<<<BATCH / ROWS_PER_CTA, NTHREADS>>>(stm_idx, nstm_idx, values,
                                                        b_ft, W_out, b_out, out);
}